// round 4
// baseline (speedup 1.0000x reference)
#include <cuda_runtime.h>
#include <math.h>

#define NMAX 100000
#define EMAX 1600000
#define D 64
#define KDIM 192
#define OUTC 64

typedef unsigned long long u64;

// ---- scratch ----
__device__ int   g_cnt[NMAX];
__device__ int   g_start[NMAX + 1];
__device__ int   g_cursor[NMAX];
__device__ int   g_adj[EMAX];
__device__ int   g_bsum[260];
__device__ int   g_total;
__device__ float g_comb[(size_t)NMAX * KDIM];   // [N, 192] sum|max|min

// ---------------- CSR build ----------------

__global__ void zero_cnt_kernel(int n) {
    int i = blockIdx.x * blockDim.x + threadIdx.x;
    if (i < n) g_cnt[i] = 0;
}

// MLP=4 histogram: 4 independent strided elements per thread
__global__ __launch_bounds__(256) void hist_kernel(const int* __restrict__ row, int E, int S) {
    int i = blockIdx.x * blockDim.x + threadIdx.x;
    int i1 = i + S, i2 = i + 2 * S, i3 = i + 3 * S;
    int r0 = (i  < E) ? row[i]  : -1;
    int r1 = (i1 < E) ? row[i1] : -1;
    int r2 = (i2 < E) ? row[i2] : -1;
    int r3 = (i3 < E) ? row[i3] : -1;
    if (r0 >= 0) atomicAdd(&g_cnt[r0], 1);
    if (r1 >= 0) atomicAdd(&g_cnt[r1], 1);
    if (r2 >= 0) atomicAdd(&g_cnt[r2], 1);
    if (r3 >= 0) atomicAdd(&g_cnt[r3], 1);
}

// ---- hierarchical scan: SCAN_B=512 per block ----
#define SCAN_B 512

__global__ __launch_bounds__(SCAN_B) void scan_partial_kernel(int n) {
    __shared__ int ws[16];
    int blk = blockIdx.x, tid = threadIdx.x;
    int i = blk * SCAN_B + tid;
    int v = (i < n) ? g_cnt[i] : 0;
    int lane = tid & 31, wid = tid >> 5;
    int x = v;
    #pragma unroll
    for (int o = 1; o < 32; o <<= 1) {
        int y = __shfl_up_sync(0xffffffffu, x, o);
        if (lane >= o) x += y;
    }
    if (lane == 31) ws[wid] = x;
    __syncthreads();
    if (wid == 0 && lane < 16) {
        int w = ws[lane];
        #pragma unroll
        for (int o = 1; o < 16; o <<= 1) {
            int y = __shfl_up_sync(0x0000ffffu, w, o);
            if (lane >= o) w += y;
        }
        ws[lane] = w;
    }
    __syncthreads();
    int incl = x + (wid > 0 ? ws[wid - 1] : 0);
    if (i < n) g_start[i] = incl - v;          // block-local exclusive
    if (tid == SCAN_B - 1) g_bsum[blk] = incl; // block total
}

__global__ __launch_bounds__(256) void scan_bsums_kernel(int nb) {
    __shared__ int ws[8];
    int tid = threadIdx.x;
    int v = (tid < nb) ? g_bsum[tid] : 0;
    int lane = tid & 31, wid = tid >> 5;
    int x = v;
    #pragma unroll
    for (int o = 1; o < 32; o <<= 1) {
        int y = __shfl_up_sync(0xffffffffu, x, o);
        if (lane >= o) x += y;
    }
    if (lane == 31) ws[wid] = x;
    __syncthreads();
    if (wid == 0 && lane < 8) {
        int w = ws[lane];
        #pragma unroll
        for (int o = 1; o < 8; o <<= 1) {
            int y = __shfl_up_sync(0x000000ffu, w, o);
            if (lane >= o) w += y;
        }
        ws[lane] = w;
    }
    __syncthreads();
    int incl = x + (wid > 0 ? ws[wid - 1] : 0);
    g_bsum[tid] = incl - v;                    // exclusive block offsets
    if (tid == 255) g_total = incl;
}

__global__ __launch_bounds__(SCAN_B) void scan_add_kernel(int n) {
    int i = blockIdx.x * SCAN_B + threadIdx.x;
    if (i < n) {
        int s = g_start[i] + g_bsum[blockIdx.x];
        g_start[i] = s;
        g_cursor[i] = s;
    }
    if (i == 0) g_start[n] = g_total;
}

// MLP=4 scatter: preload 4 (row,col), 4 independent atomics in flight, 4 stores
__global__ __launch_bounds__(256) void scatter_kernel(const int* __restrict__ row,
                                                      const int* __restrict__ col,
                                                      int E, int S) {
    int i = blockIdx.x * blockDim.x + threadIdx.x;
    int i1 = i + S, i2 = i + 2 * S, i3 = i + 3 * S;
    int r0 = (i  < E) ? row[i]  : -1;
    int r1 = (i1 < E) ? row[i1] : -1;
    int r2 = (i2 < E) ? row[i2] : -1;
    int r3 = (i3 < E) ? row[i3] : -1;
    int c0 = (i  < E) ? col[i]  : 0;
    int c1 = (i1 < E) ? col[i1] : 0;
    int c2 = (i2 < E) ? col[i2] : 0;
    int c3 = (i3 < E) ? col[i3] : 0;
    int p0 = (r0 >= 0) ? atomicAdd(&g_cursor[r0], 1) : 0;
    int p1 = (r1 >= 0) ? atomicAdd(&g_cursor[r1], 1) : 0;
    int p2 = (r2 >= 0) ? atomicAdd(&g_cursor[r2], 1) : 0;
    int p3 = (r3 >= 0) ? atomicAdd(&g_cursor[r3], 1) : 0;
    if (r0 >= 0) g_adj[p0] = c0;
    if (r1 >= 0) g_adj[p1] = c1;
    if (r2 >= 0) g_adj[p2] = c2;
    if (r3 >= 0) g_adj[p3] = c3;
}

// ---------------- aggregation: half-warp per node, batched index prefetch ----------------
// 16 lanes x float4 = 64 dims. Indices for up to 16 edges loaded coalesced in one
// LDG per lane, then shuffled out; inner loop issues 4 independent gathers (MLP=4).

__device__ __forceinline__ void acc4(float4& sm, float4& mx, float4& mn, float4 f) {
    sm.x += f.x;  sm.y += f.y;  sm.z += f.z;  sm.w += f.w;
    mx.x = fmaxf(mx.x, f.x);  mx.y = fmaxf(mx.y, f.y);
    mx.z = fmaxf(mx.z, f.z);  mx.w = fmaxf(mx.w, f.w);
    mn.x = fminf(mn.x, f.x);  mn.y = fminf(mn.y, f.y);
    mn.z = fminf(mn.z, f.z);  mn.w = fminf(mn.w, f.w);
}

__global__ __launch_bounds__(256) void aggregate_kernel(const float* __restrict__ feat, int n) {
    int gt   = blockIdx.x * blockDim.x + threadIdx.x;
    int node = gt >> 4;
    int lane = gt & 15;                       // lane within half-warp
    if (node >= n) return;
    int base = (threadIdx.x >> 4 & 1) * 16;   // half-warp base lane within warp
    unsigned hmask = 0xFFFFu << base;

    int s = g_start[node];
    int e = g_start[node + 1];

    float4 sm = make_float4(0.f, 0.f, 0.f, 0.f);
    float4 mx = make_float4(-INFINITY, -INFINITY, -INFINITY, -INFINITY);
    float4 mn = make_float4( INFINITY,  INFINITY,  INFINITY,  INFINITY);

    for (int jb = s; jb < e; jb += 16) {
        int cnt = min(16, e - jb);
        int myIdx = (jb + lane < e) ? g_adj[jb + lane] : 0;   // coalesced 64B
        int k = 0;
        for (; k + 4 <= cnt; k += 4) {
            int c0 = __shfl_sync(hmask, myIdx, base + k);
            int c1 = __shfl_sync(hmask, myIdx, base + k + 1);
            int c2 = __shfl_sync(hmask, myIdx, base + k + 2);
            int c3 = __shfl_sync(hmask, myIdx, base + k + 3);
            float4 f0 = *(const float4*)&feat[(size_t)c0 * D + 4 * lane];
            float4 f1 = *(const float4*)&feat[(size_t)c1 * D + 4 * lane];
            float4 f2 = *(const float4*)&feat[(size_t)c2 * D + 4 * lane];
            float4 f3 = *(const float4*)&feat[(size_t)c3 * D + 4 * lane];
            acc4(sm, mx, mn, f0);
            acc4(sm, mx, mn, f1);
            acc4(sm, mx, mn, f2);
            acc4(sm, mx, mn, f3);
        }
        for (; k < cnt; k++) {
            int c0 = __shfl_sync(hmask, myIdx, base + k);
            float4 f0 = *(const float4*)&feat[(size_t)c0 * D + 4 * lane];
            acc4(sm, mx, mn, f0);
        }
    }
    if (e == s) {
        mx = make_float4(0.f, 0.f, 0.f, 0.f);
        mn = make_float4(0.f, 0.f, 0.f, 0.f);
    }

    float* cb = &g_comb[(size_t)node * KDIM];
    *(float4*)&cb[        4 * lane] = sm;
    *(float4*)&cb[ D  +   4 * lane] = mx;
    *(float4*)&cb[2*D +   4 * lane] = mn;
}

// ---------------- MLP GEMM with packed f32x2 FMA ----------------

__device__ __forceinline__ u64 pack2(float lo, float hi) {
    u64 r; asm("mov.b64 %0, {%1, %2};" : "=l"(r) : "f"(lo), "f"(hi)); return r;
}
__device__ __forceinline__ void ffma2(u64& d, u64 a, u64 b) {
    asm("fma.rn.f32x2 %0, %1, %2, %0;" : "+l"(d) : "l"(a), "l"(b));
}
__device__ __forceinline__ float2 unpack2(u64 v) {
    float2 f; asm("mov.b64 {%0, %1}, %2;" : "=f"(f.x), "=f"(f.y) : "l"(v)); return f;
}

#define BM 128
#define BK 16
#define BN 64

__global__ __launch_bounds__(256) void mlp_gemm_kernel(
    const float* __restrict__ Wg,     // [192,64]
    const float* __restrict__ bg,     // [64]
    float* __restrict__ out, int n)
{
    __shared__ float As[BK][BM];
    __shared__ float Bs[BK][BN];

    const float* __restrict__ A = g_comb;

    int tid = threadIdx.x;
    int block_m = blockIdx.x * BM;
    int tx = tid & 15;                // 4 output cols
    int ty = tid >> 4;                // 8 output rows (4 row-pairs)

    int a_row  = tid >> 2;
    int a_col4 = (tid & 3) * 4;
    int b_row  = tid >> 4;
    int b_col4 = (tid & 15) * 4;

    u64 acc[4][4];                    // [row-pair][col] packed f32x2
    #pragma unroll
    for (int i = 0; i < 4; i++)
        #pragma unroll
        for (int j = 0; j < 4; j++) acc[i][j] = 0ull;

    for (int k0 = 0; k0 < KDIM; k0 += BK) {
        #pragma unroll
        for (int r = 0; r < 2; r++) {
            int m  = a_row + r * 64;
            int gm = block_m + m;
            float4 v = make_float4(0.f, 0.f, 0.f, 0.f);
            if (gm < n) v = *(const float4*)&A[(size_t)gm * KDIM + k0 + a_col4];
            As[a_col4 + 0][m] = v.x;
            As[a_col4 + 1][m] = v.y;
            As[a_col4 + 2][m] = v.z;
            As[a_col4 + 3][m] = v.w;
        }
        *(float4*)&Bs[b_row][b_col4] =
            *(const float4*)&Wg[(size_t)(k0 + b_row) * BN + b_col4];
        __syncthreads();

        #pragma unroll
        for (int k = 0; k < BK; k++) {
            u64 ra[4];
            #pragma unroll
            for (int i = 0; i < 4; i++)
                ra[i] = *(const u64*)&As[k][ty * 8 + 2 * i];   // LDS.64, row pair
            float4 rbv = *(const float4*)&Bs[k][tx * 4];
            u64 rb[4];
            rb[0] = pack2(rbv.x, rbv.x);
            rb[1] = pack2(rbv.y, rbv.y);
            rb[2] = pack2(rbv.z, rbv.z);
            rb[3] = pack2(rbv.w, rbv.w);
            #pragma unroll
            for (int i = 0; i < 4; i++)
                #pragma unroll
                for (int j = 0; j < 4; j++)
                    ffma2(acc[i][j], ra[i], rb[j]);
        }
        __syncthreads();
    }

    float4 bv = *(const float4*)&bg[tx * 4];
    #pragma unroll
    for (int i = 0; i < 4; i++) {
        float2 c0 = unpack2(acc[i][0]);
        float2 c1 = unpack2(acc[i][1]);
        float2 c2 = unpack2(acc[i][2]);
        float2 c3 = unpack2(acc[i][3]);
        int gm0 = block_m + ty * 8 + 2 * i;
        if (gm0 < n) {
            float4 o;
            o.x = tanhf(c0.x + bv.x); o.y = tanhf(c1.x + bv.y);
            o.z = tanhf(c2.x + bv.z); o.w = tanhf(c3.x + bv.w);
            *(float4*)&out[(size_t)gm0 * OUTC + tx * 4] = o;
        }
        if (gm0 + 1 < n) {
            float4 o;
            o.x = tanhf(c0.y + bv.x); o.y = tanhf(c1.y + bv.y);
            o.z = tanhf(c2.y + bv.z); o.w = tanhf(c3.y + bv.w);
            *(float4*)&out[(size_t)(gm0 + 1) * OUTC + tx * 4] = o;
        }
    }
}

// ---------------- launch ----------------

extern "C" void kernel_launch(void* const* d_in, const int* in_sizes, int n_in,
                              void* d_out, int out_size) {
    const int*   row  = (const int*)d_in[0];
    const int*   col  = (const int*)d_in[1];
    const float* feat = (const float*)d_in[2];
    const float* W    = (const float*)d_in[3];
    const float* b    = (const float*)d_in[4];
    float* out = (float*)d_out;

    int E = in_sizes[0];
    int N = in_sizes[2] / D;
    int nb = (N + SCAN_B - 1) / SCAN_B;

    int quarter = (E + 3) / 4;                    // elements per strided pass
    int eblocks = (quarter + 255) / 256;
    int S = eblocks * 256;                        // stride between the 4 passes

    zero_cnt_kernel<<<(N + 255) / 256, 256>>>(N);
    hist_kernel<<<eblocks, 256>>>(row, E, S);
    scan_partial_kernel<<<nb, SCAN_B>>>(N);
    scan_bsums_kernel<<<1, 256>>>(nb);
    scan_add_kernel<<<nb, SCAN_B>>>(N);
    scatter_kernel<<<eblocks, 256>>>(row, col, E, S);
    aggregate_kernel<<<(N * 16 + 255) / 256, 256>>>(feat, N);
    mlp_gemm_kernel<<<(N + BM - 1) / BM, 256>>>(W, b, out, N);
}

// round 5
// speedup vs baseline: 1.0823x; 1.0823x over previous
#include <cuda_runtime.h>
#include <math.h>

#define NMAX 100000
#define EMAX 1600000
#define D 64
#define KDIM 192
#define OUTC 64

typedef unsigned long long u64;

// ---- scratch ----
__device__ int   g_cnt[NMAX];
__device__ int   g_start[NMAX + 1];
__device__ int   g_cursor[NMAX];
__device__ int   g_adj[EMAX];
__device__ int   g_bsum[260];
__device__ int   g_total;
__device__ float g_comb[(size_t)NMAX * KDIM];   // [N, 192] sum|max|min

// ---------------- CSR build ----------------

__global__ void zero_cnt_kernel(int n) {
    int i = blockIdx.x * blockDim.x + threadIdx.x;
    if (i < n) g_cnt[i] = 0;
}

__global__ void hist_kernel(const int* __restrict__ row, int E) {
    int i = blockIdx.x * blockDim.x + threadIdx.x;
    if (i < E) atomicAdd(&g_cnt[row[i]], 1);
}

// ---- hierarchical scan: SCAN_B=512 per block ----
#define SCAN_B 512

__global__ __launch_bounds__(SCAN_B) void scan_partial_kernel(int n) {
    __shared__ int ws[16];
    int blk = blockIdx.x, tid = threadIdx.x;
    int i = blk * SCAN_B + tid;
    int v = (i < n) ? g_cnt[i] : 0;
    int lane = tid & 31, wid = tid >> 5;
    int x = v;
    #pragma unroll
    for (int o = 1; o < 32; o <<= 1) {
        int y = __shfl_up_sync(0xffffffffu, x, o);
        if (lane >= o) x += y;
    }
    if (lane == 31) ws[wid] = x;
    __syncthreads();
    if (wid == 0 && lane < 16) {
        int w = ws[lane];
        #pragma unroll
        for (int o = 1; o < 16; o <<= 1) {
            int y = __shfl_up_sync(0x0000ffffu, w, o);
            if (lane >= o) w += y;
        }
        ws[lane] = w;
    }
    __syncthreads();
    int incl = x + (wid > 0 ? ws[wid - 1] : 0);
    if (i < n) g_start[i] = incl - v;          // block-local exclusive
    if (tid == SCAN_B - 1) g_bsum[blk] = incl; // block total
}

__global__ __launch_bounds__(256) void scan_bsums_kernel(int nb) {
    __shared__ int ws[8];
    int tid = threadIdx.x;
    int v = (tid < nb) ? g_bsum[tid] : 0;
    int lane = tid & 31, wid = tid >> 5;
    int x = v;
    #pragma unroll
    for (int o = 1; o < 32; o <<= 1) {
        int y = __shfl_up_sync(0xffffffffu, x, o);
        if (lane >= o) x += y;
    }
    if (lane == 31) ws[wid] = x;
    __syncthreads();
    if (wid == 0 && lane < 8) {
        int w = ws[lane];
        #pragma unroll
        for (int o = 1; o < 8; o <<= 1) {
            int y = __shfl_up_sync(0x000000ffu, w, o);
            if (lane >= o) w += y;
        }
        ws[lane] = w;
    }
    __syncthreads();
    int incl = x + (wid > 0 ? ws[wid - 1] : 0);
    g_bsum[tid] = incl - v;                    // exclusive block offsets
    if (tid == 255) g_total = incl;
}

__global__ __launch_bounds__(SCAN_B) void scan_add_kernel(int n) {
    int i = blockIdx.x * SCAN_B + threadIdx.x;
    if (i < n) {
        int s = g_start[i] + g_bsum[blockIdx.x];
        g_start[i] = s;
        g_cursor[i] = s;
    }
    if (i == 0) g_start[n] = g_total;
}

__global__ void scatter_kernel(const int* __restrict__ row,
                               const int* __restrict__ col, int E) {
    int i = blockIdx.x * blockDim.x + threadIdx.x;
    if (i < E) {
        int p = atomicAdd(&g_cursor[row[i]], 1);
        g_adj[p] = col[i];
    }
}

// ---------------- aggregation: half-warp per node, broadcast indices ----------------
// 16 lanes x float4 = 64 dims. 4-edge unroll: 4 independent broadcast index loads
// then 4 independent float4 gathers in flight (MLP=4). No shuffles.

__device__ __forceinline__ void acc4(float4& sm, float4& mx, float4& mn, float4 f) {
    sm.x += f.x;  sm.y += f.y;  sm.z += f.z;  sm.w += f.w;
    mx.x = fmaxf(mx.x, f.x);  mx.y = fmaxf(mx.y, f.y);
    mx.z = fmaxf(mx.z, f.z);  mx.w = fmaxf(mx.w, f.w);
    mn.x = fminf(mn.x, f.x);  mn.y = fminf(mn.y, f.y);
    mn.z = fminf(mn.z, f.z);  mn.w = fminf(mn.w, f.w);
}

__global__ __launch_bounds__(256) void aggregate_kernel(const float* __restrict__ feat, int n) {
    int gt   = blockIdx.x * blockDim.x + threadIdx.x;
    int node = gt >> 4;
    int lane = gt & 15;
    if (node >= n) return;

    int s = g_start[node];
    int e = g_start[node + 1];

    float4 sm = make_float4(0.f, 0.f, 0.f, 0.f);
    float4 mx = make_float4(-INFINITY, -INFINITY, -INFINITY, -INFINITY);
    float4 mn = make_float4( INFINITY,  INFINITY,  INFINITY,  INFINITY);

    int j = s;
    for (; j + 4 <= e; j += 4) {
        int c0 = __ldg(&g_adj[j]);
        int c1 = __ldg(&g_adj[j + 1]);
        int c2 = __ldg(&g_adj[j + 2]);
        int c3 = __ldg(&g_adj[j + 3]);
        float4 f0 = *(const float4*)&feat[(size_t)c0 * D + 4 * lane];
        float4 f1 = *(const float4*)&feat[(size_t)c1 * D + 4 * lane];
        float4 f2 = *(const float4*)&feat[(size_t)c2 * D + 4 * lane];
        float4 f3 = *(const float4*)&feat[(size_t)c3 * D + 4 * lane];
        acc4(sm, mx, mn, f0);
        acc4(sm, mx, mn, f1);
        acc4(sm, mx, mn, f2);
        acc4(sm, mx, mn, f3);
    }
    for (; j < e; j++) {
        int c0 = __ldg(&g_adj[j]);
        float4 f0 = *(const float4*)&feat[(size_t)c0 * D + 4 * lane];
        acc4(sm, mx, mn, f0);
    }
    if (e == s) {
        mx = make_float4(0.f, 0.f, 0.f, 0.f);
        mn = make_float4(0.f, 0.f, 0.f, 0.f);
    }

    float* cb = &g_comb[(size_t)node * KDIM];
    *(float4*)&cb[        4 * lane] = sm;
    *(float4*)&cb[ D  +   4 * lane] = mx;
    *(float4*)&cb[2*D +   4 * lane] = mn;
}

// ---------------- MLP GEMM with packed f32x2 FMA ----------------

__device__ __forceinline__ u64 pack2(float lo, float hi) {
    u64 r; asm("mov.b64 %0, {%1, %2};" : "=l"(r) : "f"(lo), "f"(hi)); return r;
}
__device__ __forceinline__ void ffma2(u64& d, u64 a, u64 b) {
    asm("fma.rn.f32x2 %0, %1, %2, %0;" : "+l"(d) : "l"(a), "l"(b));
}
__device__ __forceinline__ float2 unpack2(u64 v) {
    float2 f; asm("mov.b64 {%0, %1}, %2;" : "=f"(f.x), "=f"(f.y) : "l"(v)); return f;
}

#define BM 128
#define BK 16
#define BN 64

__global__ __launch_bounds__(256) void mlp_gemm_kernel(
    const float* __restrict__ Wg,     // [192,64]
    const float* __restrict__ bg,     // [64]
    float* __restrict__ out, int n)
{
    __shared__ float As[BK][BM];
    __shared__ float Bs[BK][BN];

    const float* __restrict__ A = g_comb;

    int tid = threadIdx.x;
    int block_m = blockIdx.x * BM;
    int tx = tid & 15;                // 4 output cols
    int ty = tid >> 4;                // 8 output rows (4 row-pairs)

    int a_row  = tid >> 2;
    int a_col4 = (tid & 3) * 4;
    int b_row  = tid >> 4;
    int b_col4 = (tid & 15) * 4;

    u64 acc[4][4];                    // [row-pair][col] packed f32x2
    #pragma unroll
    for (int i = 0; i < 4; i++)
        #pragma unroll
        for (int j = 0; j < 4; j++) acc[i][j] = 0ull;

    for (int k0 = 0; k0 < KDIM; k0 += BK) {
        #pragma unroll
        for (int r = 0; r < 2; r++) {
            int m  = a_row + r * 64;
            int gm = block_m + m;
            float4 v = make_float4(0.f, 0.f, 0.f, 0.f);
            if (gm < n) v = *(const float4*)&A[(size_t)gm * KDIM + k0 + a_col4];
            As[a_col4 + 0][m] = v.x;
            As[a_col4 + 1][m] = v.y;
            As[a_col4 + 2][m] = v.z;
            As[a_col4 + 3][m] = v.w;
        }
        *(float4*)&Bs[b_row][b_col4] =
            *(const float4*)&Wg[(size_t)(k0 + b_row) * BN + b_col4];
        __syncthreads();

        #pragma unroll
        for (int k = 0; k < BK; k++) {
            u64 ra[4];
            #pragma unroll
            for (int i = 0; i < 4; i++)
                ra[i] = *(const u64*)&As[k][ty * 8 + 2 * i];   // LDS.64, row pair
            float4 rbv = *(const float4*)&Bs[k][tx * 4];
            u64 rb[4];
            rb[0] = pack2(rbv.x, rbv.x);
            rb[1] = pack2(rbv.y, rbv.y);
            rb[2] = pack2(rbv.z, rbv.z);
            rb[3] = pack2(rbv.w, rbv.w);
            #pragma unroll
            for (int i = 0; i < 4; i++)
                #pragma unroll
                for (int j = 0; j < 4; j++)
                    ffma2(acc[i][j], ra[i], rb[j]);
        }
        __syncthreads();
    }

    float4 bv = *(const float4*)&bg[tx * 4];
    #pragma unroll
    for (int i = 0; i < 4; i++) {
        float2 c0 = unpack2(acc[i][0]);
        float2 c1 = unpack2(acc[i][1]);
        float2 c2 = unpack2(acc[i][2]);
        float2 c3 = unpack2(acc[i][3]);
        int gm0 = block_m + ty * 8 + 2 * i;
        if (gm0 < n) {
            float4 o;
            o.x = tanhf(c0.x + bv.x); o.y = tanhf(c1.x + bv.y);
            o.z = tanhf(c2.x + bv.z); o.w = tanhf(c3.x + bv.w);
            *(float4*)&out[(size_t)gm0 * OUTC + tx * 4] = o;
        }
        if (gm0 + 1 < n) {
            float4 o;
            o.x = tanhf(c0.y + bv.x); o.y = tanhf(c1.y + bv.y);
            o.z = tanhf(c2.y + bv.z); o.w = tanhf(c3.y + bv.w);
            *(float4*)&out[(size_t)(gm0 + 1) * OUTC + tx * 4] = o;
        }
    }
}

// ---------------- launch ----------------

extern "C" void kernel_launch(void* const* d_in, const int* in_sizes, int n_in,
                              void* d_out, int out_size) {
    const int*   row  = (const int*)d_in[0];
    const int*   col  = (const int*)d_in[1];
    const float* feat = (const float*)d_in[2];
    const float* W    = (const float*)d_in[3];
    const float* b    = (const float*)d_in[4];
    float* out = (float*)d_out;

    int E = in_sizes[0];
    int N = in_sizes[2] / D;
    int nb = (N + SCAN_B - 1) / SCAN_B;

    zero_cnt_kernel<<<(N + 255) / 256, 256>>>(N);
    hist_kernel<<<(E + 255) / 256, 256>>>(row, E);
    scan_partial_kernel<<<nb, SCAN_B>>>(N);
    scan_bsums_kernel<<<1, 256>>>(nb);
    scan_add_kernel<<<nb, SCAN_B>>>(N);
    scatter_kernel<<<(E + 255) / 256, 256>>>(row, col, E);
    aggregate_kernel<<<(N * 16 + 255) / 256, 256>>>(feat, N);
    mlp_gemm_kernel<<<(N + BM - 1) / BM, 256>>>(W, b, out, N);
}